// round 15
// baseline (speedup 1.0000x reference)
#include <cuda_runtime.h>

// ProjectionLoss fused single-kernel: packed-operand f32x2 + shared-fold j-split
// + 48-reg occupancy push (launch_bounds(128,10) -> 10 blocks/SM, 62.5% occ cap).
//   R6..R14 showed the kernel is scheduling-bound: no pipe >40%, issue ~60%,
//   occ capped at 42% by regs=64. This round trades register headroom (full
//   unroll -> unroll 4, tighter live ranges) for +47% resident warps.
//   - Keypoints staged INTERLEAVED in smem: packed f32x2 operands, no movs.
//   - Folded matrices computed ONCE per (b,view) into smem as (gt,pred) pairs.
//   - Matvec: 9 fma.rn.f32x2 per point-view. One rcp per TWO points.
//   - Smooth-MSE: min(d2, ex2(fma(lg2(d2),0.1,log2(400^0.9)))), branch-free.
//   - Tail: last-arriving block reduces per-block partials in fixed order.

#define B_TOTAL 16384
#define V_NUM   8
#define J_NUM   64
#define NB      8                       // batch elements per block
#define JSPLIT  2                       // j-split threads per (b,view)
#define THREADS (NB * V_NUM * JSPLIT)   // 128
#define NBLOCKS (B_TOTAL / NB)          // 2048
#define JPAIRS  (J_NUM / 2 / JSPLIT)    // 16 joint-pairs per thread

#define XPSTR   392                     // padded floats per b (384 + 8 pad)

#define LOG2_POWC 7.77947056f           // log2(400^0.9)

__device__ float g_partials[NBLOCKS];
__device__ int   g_count = 0;

typedef unsigned long long u64;

__device__ __forceinline__ void upk2(float& lo, float& hi, u64 v) {
    asm("mov.b64 {%0, %1}, %2;" : "=f"(lo), "=f"(hi) : "l"(v));
}
__device__ __forceinline__ u64 fma2(u64 a, u64 b, u64 c) {
    u64 d; asm("fma.rn.f32x2 %0, %1, %2, %3;" : "=l"(d) : "l"(a), "l"(b), "l"(c)); return d;
}
__device__ __forceinline__ float rcpa(float x) {
    float r; asm("rcp.approx.f32 %0, %1;" : "=f"(r) : "f"(x)); return r;
}
__device__ __forceinline__ float lg2a(float x) {
    float r; asm("lg2.approx.f32 %0, %1;" : "=f"(r) : "f"(x)); return r;
}
__device__ __forceinline__ float ex2a(float x) {
    float r; asm("ex2.approx.f32 %0, %1;" : "=f"(r) : "f"(x)); return r;
}
__device__ __forceinline__ float smooth_term(float d2) {
    // exact rewrite of: d2>400 ? d2^0.1 * 400^0.9 : d2 (pow branch >= d2 iff d2<=400)
    float p = ex2a(fmaf(lg2a(d2), 0.1f, LOG2_POWC));
    return fminf(d2, p);
}

__global__ __launch_bounds__(THREADS, 10)
void proj_loss_fused(const float* __restrict__ gt_kps,
                     const float* __restrict__ pr_kps,
                     const float* __restrict__ gt_R,
                     const float* __restrict__ gt_t,
                     const float* __restrict__ Kmat,
                     const float* __restrict__ cam,
                     float* __restrict__ out)
{
    __shared__ __align__(16) float sXP[NB * XPSTR];          // 3136 floats
    __shared__ __align__(16) float sFold[NB * V_NUM * 24];   // 1536
    __shared__ float sWarp[THREADS / 32];
    __shared__ int   sIsLast;

    const int tid = threadIdx.x;
    const long b0 = (long)blockIdx.x * NB;

    // ---- stage keypoints INTERLEAVED: per joint (X0,P0)(X1,P1)(X2,P2) ----
    {
        const float4* g4 = (const float4*)(gt_kps + b0 * (J_NUM * 3));
        const float4* p4 = (const float4*)(pr_kps + b0 * (J_NUM * 3));
        for (int i = tid; i < NB * J_NUM * 3 / 4; i += THREADS) {
            const int b  = i / 48;          // 48 float4 per batch element
            const int iw = i - b * 48;
            float4 g = g4[i];
            float4 p = p4[i];
            float4* dst = (float4*)(sXP + b * XPSTR) + 2 * iw;
            dst[0] = make_float4(g.x, p.x, g.y, p.y);
            dst[1] = make_float4(g.z, p.z, g.w, p.w);
        }
    }

    // ---- fold phase: 64 threads, ONE fold per (b,v), packed (g,p) pairs ----
    if (tid < NB * V_NUM) {
        const int fbl = tid >> 3;       // 0..7
        const int fv  = tid & 7;        // 0..7
        const float* k  = Kmat + fv * 9;
        const float* R  = gt_R + (b0 + fbl) * (V_NUM * 9)  + fv * 9;
        const float* t  = gt_t + (b0 + fbl) * (V_NUM * 3)  + fv * 3;
        const float* cm = cam  + (b0 + fbl) * (V_NUM * 12) + fv * 12;
        float2* rec = (float2*)&sFold[tid * 24];
        #pragma unroll
        for (int r = 0; r < 3; r++) {
            float k0 = k[r * 3 + 0], k1 = k[r * 3 + 1], k2 = k[r * 3 + 2];
            #pragma unroll
            for (int c = 0; c < 3; c++) {
                float g = fmaf(k0, R[c], fmaf(k1, R[3 + c], k2 * R[6 + c]));
                float p = fmaf(k0, cm[c], fmaf(k1, cm[4 + c], k2 * cm[8 + c]));
                rec[r * 4 + c] = make_float2(g, p);
            }
            float g3 = fmaf(k0, t[0], fmaf(k1, t[1], k2 * t[2]));
            float p3 = fmaf(k0, cm[3], fmaf(k1, cm[7], k2 * cm[11]));
            rec[r * 4 + 3] = make_float2(g3, p3);
        }
    }
    __syncthreads();

    // ---- consumer mapping: bl | v | jh ----
    const int bl = tid >> 4;            // 0..7
    const int v  = (tid >> 1) & 7;      // 0..7
    const int jh = tid & 1;             // 0..1

    // recover packed GC[12] via 6 broadcast LDS.128
    u64 GC[12];
    {
        const ulonglong2* f2 = (const ulonglong2*)&sFold[((bl << 3) + v) * 24];
        #pragma unroll
        for (int i = 0; i < 6; i++) {
            ulonglong2 q = f2[i];
            GC[i * 2 + 0] = q.x;
            GC[i * 2 + 1] = q.y;
        }
    }

    const ulonglong2* xp2 = (const ulonglong2*)(sXP)
                          + bl * (XPSTR / 4) + jh * (JPAIRS * 3);

    float accx = 0.0f, accy = 0.0f;

    // ---- main loop: 16 joint-pairs, unroll 4 (register-pressure friendly) ----
    #pragma unroll 4
    for (int q = 0; q < JPAIRS; q++) {
        const ulonglong2 qa = xp2[q * 3 + 0];   // (X0P0 A, X1P1 A)
        const ulonglong2 qb = xp2[q * 3 + 1];   // (X2P2 A, X0P0 B)
        const ulonglong2 qc = xp2[q * 3 + 2];   // (X1P1 B, X2P2 B)

        u64 uuA = fma2(GC[0], qa.x, fma2(GC[1], qa.y, fma2(GC[2],  qb.x, GC[3])));
        u64 vvA = fma2(GC[4], qa.x, fma2(GC[5], qa.y, fma2(GC[6],  qb.x, GC[7])));
        u64 wwA = fma2(GC[8], qa.x, fma2(GC[9], qa.y, fma2(GC[10], qb.x, GC[11])));

        u64 uuB = fma2(GC[0], qb.y, fma2(GC[1], qc.x, fma2(GC[2],  qc.y, GC[3])));
        u64 vvB = fma2(GC[4], qb.y, fma2(GC[5], qc.x, fma2(GC[6],  qc.y, GC[7])));
        u64 wwB = fma2(GC[8], qb.y, fma2(GC[9], qc.x, fma2(GC[10], qc.y, GC[11])));

        float uA, upA;  upk2(uA, upA, uuA);
        float vA, vpA;  upk2(vA, vpA, vvA);
        float wA, wpA;  upk2(wA, wpA, wwA);
        float uB, upB;  upk2(uB, upB, uuB);
        float vB, vpB;  upk2(vB, vpB, vvB);
        float wB, wpB;  upk2(wB, wpB, wwB);

        float zA = wA * wpA;
        float zB = wB * wpB;
        float rr = rcpa(zA * zB);
        float rA = rr * zB;
        float rB = rr * zA;

        float dxA = fmaf(upA, -wA, uA * wpA) * rA;
        float dyA = fmaf(vpA, -wA, vA * wpA) * rA;
        float dxB = fmaf(upB, -wB, uB * wpB) * rB;
        float dyB = fmaf(vpB, -wB, vB * wpB) * rB;

        accx += smooth_term(dxA * dxA);
        accy += smooth_term(dyA * dyA);
        accx += smooth_term(dxB * dxB);
        accy += smooth_term(dyB * dyB);
    }

    float acc = accx + accy;

    // ---- block reduction (4 warps) ----
    #pragma unroll
    for (int o = 16; o > 0; o >>= 1)
        acc += __shfl_xor_sync(0xFFFFFFFFu, acc, o);

    const int lane = tid & 31;
    const int wid  = tid >> 5;
    if (lane == 0) sWarp[wid] = acc;
    __syncthreads();

    if (wid == 0) {
        float s = (lane < THREADS / 32) ? sWarp[lane] : 0.0f;
        #pragma unroll
        for (int o = 2; o > 0; o >>= 1)
            s += __shfl_xor_sync(0xFFFFFFFFu, s, o);
        if (lane == 0) g_partials[blockIdx.x] = s;
    }

    // ---- fused finish: last-arriving block reduces partials ----
    __threadfence();
    if (tid == 0) {
        int c = atomicAdd(&g_count, 1);
        sIsLast = (c == NBLOCKS - 1);
    }
    __syncthreads();

    if (sIsLast) {
        float s = 0.0f;
        #pragma unroll
        for (int rep = 0; rep < NBLOCKS / THREADS; rep++)
            s += g_partials[tid + rep * THREADS];

        #pragma unroll
        for (int o = 16; o > 0; o >>= 1)
            s += __shfl_xor_sync(0xFFFFFFFFu, s, o);
        if (lane == 0) sWarp[wid] = s;
        __syncthreads();

        if (wid == 0) {
            float t = (lane < THREADS / 32) ? sWarp[lane] : 0.0f;
            #pragma unroll
            for (int o = 2; o > 0; o >>= 1)
                t += __shfl_xor_sync(0xFFFFFFFFu, t, o);
            if (lane == 0) {
                out[0] = t * (1.0f / (2.0f * (float)B_TOTAL));
                g_count = 0;   // reset for next graph replay
            }
        }
    }
}

extern "C" void kernel_launch(void* const* d_in, const int* in_sizes, int n_in,
                              void* d_out, int out_size)
{
    const float* gt_kps = (const float*)d_in[0];
    const float* pr_kps = (const float*)d_in[1];
    const float* gt_R   = (const float*)d_in[2];
    const float* gt_t   = (const float*)d_in[3];
    const float* Kmat   = (const float*)d_in[4];
    const float* cam    = (const float*)d_in[5];
    float* out = (float*)d_out;

    proj_loss_fused<<<NBLOCKS, THREADS>>>(gt_kps, pr_kps, gt_R, gt_t, Kmat, cam, out);
}

// round 16
// speedup vs baseline: 1.0483x; 1.0483x over previous
#include <cuda_runtime.h>

// ProjectionLoss fused single-kernel: packed-operand f32x2 + shared-fold j-split,
// TAIL-FREE reduction: harness-visible memset node zeroes out[0]; every block
// atomicAdds its pre-scaled partial (one REDG per block, no serialized last-block
// reduction phase - R1 showed that phase alone costs ~4us).
//   Block = 8 batch x 128 threads. Thread = (b_local, view, j-half): 32 joints.
//   - Keypoints staged INTERLEAVED in smem: packed f32x2 operands, no movs.
//   - Folded matrices computed ONCE per (b,view) into smem as (gt,pred) pairs.
//   - Matvec: 9 fma.rn.f32x2 per point-view. One rcp per TWO points.
//   - Smooth-MSE: min(d2, ex2(fma(lg2(d2),0.1,log2(400^0.9)))), branch-free.

#define B_TOTAL 16384
#define V_NUM   8
#define J_NUM   64
#define NB      8                       // batch elements per block
#define JSPLIT  2                       // j-split threads per (b,view)
#define THREADS (NB * V_NUM * JSPLIT)   // 128
#define NBLOCKS (B_TOTAL / NB)          // 2048
#define JPAIRS  (J_NUM / 2 / JSPLIT)    // 16 joint-pairs per thread

#define XPSTR   392                     // padded floats per b (384 + 8 pad)

#define LOG2_POWC 7.77947056f           // log2(400^0.9)
#define OUT_SCALE (1.0f / (2.0f * (float)B_TOTAL))

typedef unsigned long long u64;

__device__ __forceinline__ void upk2(float& lo, float& hi, u64 v) {
    asm("mov.b64 {%0, %1}, %2;" : "=f"(lo), "=f"(hi) : "l"(v));
}
__device__ __forceinline__ u64 fma2(u64 a, u64 b, u64 c) {
    u64 d; asm("fma.rn.f32x2 %0, %1, %2, %3;" : "=l"(d) : "l"(a), "l"(b), "l"(c)); return d;
}
__device__ __forceinline__ float rcpa(float x) {
    float r; asm("rcp.approx.f32 %0, %1;" : "=f"(r) : "f"(x)); return r;
}
__device__ __forceinline__ float lg2a(float x) {
    float r; asm("lg2.approx.f32 %0, %1;" : "=f"(r) : "f"(x)); return r;
}
__device__ __forceinline__ float ex2a(float x) {
    float r; asm("ex2.approx.f32 %0, %1;" : "=f"(r) : "f"(x)); return r;
}
__device__ __forceinline__ float smooth_term(float d2) {
    // exact rewrite of: d2>400 ? d2^0.1 * 400^0.9 : d2 (pow branch >= d2 iff d2<=400)
    float p = ex2a(fmaf(lg2a(d2), 0.1f, LOG2_POWC));
    return fminf(d2, p);
}

__global__ __launch_bounds__(THREADS, 8)
void proj_loss_fused(const float* __restrict__ gt_kps,
                     const float* __restrict__ pr_kps,
                     const float* __restrict__ gt_R,
                     const float* __restrict__ gt_t,
                     const float* __restrict__ Kmat,
                     const float* __restrict__ cam,
                     float* __restrict__ out)
{
    __shared__ __align__(16) float sXP[NB * XPSTR];          // 3136 floats
    __shared__ __align__(16) float sFold[NB * V_NUM * 24];   // 1536
    __shared__ float sWarp[THREADS / 32];

    const int tid = threadIdx.x;
    const long b0 = (long)blockIdx.x * NB;

    // ---- stage keypoints INTERLEAVED: per joint (X0,P0)(X1,P1)(X2,P2) ----
    {
        const float4* g4 = (const float4*)(gt_kps + b0 * (J_NUM * 3));
        const float4* p4 = (const float4*)(pr_kps + b0 * (J_NUM * 3));
        for (int i = tid; i < NB * J_NUM * 3 / 4; i += THREADS) {
            const int b  = i / 48;          // 48 float4 per batch element
            const int iw = i - b * 48;
            float4 g = g4[i];
            float4 p = p4[i];
            float4* dst = (float4*)(sXP + b * XPSTR) + 2 * iw;
            dst[0] = make_float4(g.x, p.x, g.y, p.y);
            dst[1] = make_float4(g.z, p.z, g.w, p.w);
        }
    }

    // ---- fold phase: 64 threads, ONE fold per (b,v), packed (g,p) pairs ----
    if (tid < NB * V_NUM) {
        const int fbl = tid >> 3;       // 0..7
        const int fv  = tid & 7;        // 0..7
        const float* k  = Kmat + fv * 9;
        const float* R  = gt_R + (b0 + fbl) * (V_NUM * 9)  + fv * 9;
        const float* t  = gt_t + (b0 + fbl) * (V_NUM * 3)  + fv * 3;
        const float* cm = cam  + (b0 + fbl) * (V_NUM * 12) + fv * 12;
        float2* rec = (float2*)&sFold[tid * 24];
        #pragma unroll
        for (int r = 0; r < 3; r++) {
            float k0 = k[r * 3 + 0], k1 = k[r * 3 + 1], k2 = k[r * 3 + 2];
            #pragma unroll
            for (int c = 0; c < 3; c++) {
                float g = fmaf(k0, R[c], fmaf(k1, R[3 + c], k2 * R[6 + c]));
                float p = fmaf(k0, cm[c], fmaf(k1, cm[4 + c], k2 * cm[8 + c]));
                rec[r * 4 + c] = make_float2(g, p);
            }
            float g3 = fmaf(k0, t[0], fmaf(k1, t[1], k2 * t[2]));
            float p3 = fmaf(k0, cm[3], fmaf(k1, cm[7], k2 * cm[11]));
            rec[r * 4 + 3] = make_float2(g3, p3);
        }
    }
    __syncthreads();

    // ---- consumer mapping: bl | v | jh ----
    const int bl = tid >> 4;            // 0..7
    const int v  = (tid >> 1) & 7;      // 0..7
    const int jh = tid & 1;             // 0..1

    // recover packed GC[12] via 6 broadcast LDS.128
    u64 GC[12];
    {
        const ulonglong2* f2 = (const ulonglong2*)&sFold[((bl << 3) + v) * 24];
        #pragma unroll
        for (int i = 0; i < 6; i++) {
            ulonglong2 q = f2[i];
            GC[i * 2 + 0] = q.x;
            GC[i * 2 + 1] = q.y;
        }
    }

    const ulonglong2* xp2 = (const ulonglong2*)(sXP)
                          + bl * (XPSTR / 4) + jh * (JPAIRS * 3);

    float accx = 0.0f, accy = 0.0f;

    // ---- main loop: 16 joint-pairs, fully unrolled ----
    #pragma unroll
    for (int q = 0; q < JPAIRS; q++) {
        const ulonglong2 qa = xp2[q * 3 + 0];   // (X0P0 A, X1P1 A)
        const ulonglong2 qb = xp2[q * 3 + 1];   // (X2P2 A, X0P0 B)
        const ulonglong2 qc = xp2[q * 3 + 2];   // (X1P1 B, X2P2 B)

        u64 uuA = fma2(GC[0], qa.x, fma2(GC[1], qa.y, fma2(GC[2],  qb.x, GC[3])));
        u64 vvA = fma2(GC[4], qa.x, fma2(GC[5], qa.y, fma2(GC[6],  qb.x, GC[7])));
        u64 wwA = fma2(GC[8], qa.x, fma2(GC[9], qa.y, fma2(GC[10], qb.x, GC[11])));

        u64 uuB = fma2(GC[0], qb.y, fma2(GC[1], qc.x, fma2(GC[2],  qc.y, GC[3])));
        u64 vvB = fma2(GC[4], qb.y, fma2(GC[5], qc.x, fma2(GC[6],  qc.y, GC[7])));
        u64 wwB = fma2(GC[8], qb.y, fma2(GC[9], qc.x, fma2(GC[10], qc.y, GC[11])));

        float uA, upA;  upk2(uA, upA, uuA);
        float vA, vpA;  upk2(vA, vpA, vvA);
        float wA, wpA;  upk2(wA, wpA, wwA);
        float uB, upB;  upk2(uB, upB, uuB);
        float vB, vpB;  upk2(vB, vpB, vvB);
        float wB, wpB;  upk2(wB, wpB, wwB);

        // one rcp for both points: rr = 1/(zA*zB)
        float zA = wA * wpA;
        float zB = wB * wpB;
        float rr = rcpa(zA * zB);
        float rA = rr * zB;
        float rB = rr * zA;

        float dxA = fmaf(upA, -wA, uA * wpA) * rA;
        float dyA = fmaf(vpA, -wA, vA * wpA) * rA;
        float dxB = fmaf(upB, -wB, uB * wpB) * rB;
        float dyB = fmaf(vpB, -wB, vB * wpB) * rB;

        accx += smooth_term(dxA * dxA);
        accy += smooth_term(dyA * dyA);
        accx += smooth_term(dxB * dxB);
        accy += smooth_term(dyB * dyB);
    }

    float acc = accx + accy;

    // ---- block reduction (4 warps) then ONE atomicAdd per block ----
    #pragma unroll
    for (int o = 16; o > 0; o >>= 1)
        acc += __shfl_xor_sync(0xFFFFFFFFu, acc, o);

    const int lane = tid & 31;
    const int wid  = tid >> 5;
    if (lane == 0) sWarp[wid] = acc;
    __syncthreads();

    if (tid == 0) {
        float s = sWarp[0] + sWarp[1] + sWarp[2] + sWarp[3];
        atomicAdd(out, s * OUT_SCALE);   // fire-and-forget REDG; no serialized tail
    }
}

extern "C" void kernel_launch(void* const* d_in, const int* in_sizes, int n_in,
                              void* d_out, int out_size)
{
    const float* gt_kps = (const float*)d_in[0];
    const float* pr_kps = (const float*)d_in[1];
    const float* gt_R   = (const float*)d_in[2];
    const float* gt_t   = (const float*)d_in[3];
    const float* Kmat   = (const float*)d_in[4];
    const float* cam    = (const float*)d_in[5];
    float* out = (float*)d_out;

    // graph-legal memset node: zero the accumulator before the grid adds into it
    cudaMemsetAsync(out, 0, sizeof(float));

    proj_loss_fused<<<NBLOCKS, THREADS>>>(gt_kps, pr_kps, gt_R, gt_t, Kmat, cam, out);
}